// round 17
// baseline (speedup 1.0000x reference)
#include <cuda_runtime.h>
#include <cuda_bf16.h>
#include <cstddef>

// Problem constants: B=512, T=1024, H=128, LAT=16, COND=1, OUT=12
#define BATCH 512
#define TT    1024
#define HID   128
#define GATES 512       // 4*H
#define OUTD  12
#define HSTR  132       // padded hbuf row stride (floats) — kills g-pair bank conflicts

typedef unsigned long long ull;

// Device scratch (static __device__ arrays are the sanctioned alloc-free workaround)
__device__ float g_hs[(size_t)BATCH * TT * HID];              // [b][t][k]  (268 MB)

// ---------------- helpers ----------------
__device__ __forceinline__ ull ffma2(ull a, ull b, ull c) {
    ull d;
    asm("fma.rn.f32x2 %0, %1, %2, %3;" : "=l"(d) : "l"(a), "l"(b), "l"(c));
    return d;
}
__device__ __forceinline__ float pairsum(ull a) {
    float lo, hi;
    asm("mov.b64 {%0, %1}, %2;" : "=f"(lo), "=f"(hi) : "l"(a));
    return lo + hi;
}
// MUFU.TANH: single-instruction tanh (sm_75+); ~2^-11 rel err.
__device__ __forceinline__ float tanhf_(float x) {
    float y;
    asm("tanh.approx.f32 %0, %1;" : "=f"(y) : "f"(x));
    return y;
}
// sigmoid(x) = 0.5*tanh(0.5x) + 0.5 : 1 MUFU + FMUL + FMA
__device__ __forceinline__ float sigmoidf_(float x) {
    return fmaf(0.5f, tanhf_(0.5f * x), 0.5f);
}

// dummy no-op kernel: keeps ncu's capture (absolute launch #6) on k2_lstm
__global__ void k_nop() {}

// ---------------- k2: xproj prologue + 1024-step recurrence ----------------
// (cell-major, row-split x split-K, 512 threads, 16 warps = 4/SMSP)
// 128 CTAs x 512 threads. CTA owns 4 batch rows.
// Lane mapping: cell_lo = lane&7, g = (lane>>3)&1, q = lane>>4.
//   cellj = warp*8 + cell_lo (0..127)
//   thread computes all 4 gates of cell cellj, rows {2g, 2g+1}, K-half q
//   (interleaved chunks 2u+q), then q-pair shfl reduce -> finalizes row 2g+q.
// Weights: gate i in REGISTERS (64 regs); gates f,g,o in smem (192 KB),
//   g=0/g=1 lanes read the SAME slot -> crossbar dedup (2 wavefronts/LDS).
// hbuf rows padded to HSTR=132 floats so g-pair h-reads are conflict-free.
// ONE __syncthreads per step; regs/thread ~105 -> 4 warps/SMSP hide latency.
// smem: wsm [48][256] ulonglong2 (196608 B) | hbuf [2][4*HSTR] f32 (4224 B)
//   => 200832 B. Prologue scratch aliases the hbuf region.
#define K2_SMEM 200832

__global__ __launch_bounds__(512, 1)
void k2_lstm(const float* __restrict__ z, const float* __restrict__ c,
             const float* __restrict__ Ws, const float* __restrict__ bs,
             const float* __restrict__ Wih, const float* __restrict__ bih,
             const float* __restrict__ bhh, const float* __restrict__ Whh) {
    extern __shared__ __align__(16) unsigned char sraw[];
    ulonglong2* wsm = (ulonglong2*)sraw;                      // [(u*3+gate)*256 + slot]
    float* hbuf = (float*)(sraw + 196608);                    // [par][r*HSTR + k]
    float* scr  = (float*)(sraw + 196608);                    // prologue scratch (aliases hbuf)

    const int tid     = threadIdx.x;
    const int lane    = tid & 31;
    const int warp    = tid >> 5;
    const int cell_lo = lane & 7;
    const int g       = (lane >> 3) & 1;                      // rowgroup
    const int q       = lane >> 4;                            // K-half (shfl partner = lane^16)
    const int cellj   = warp * 8 + cell_lo;                   // 0..127
    const int slot    = warp * 16 + cell_lo * 2 + q;          // 0..255 (g-independent!)
    const int rq      = 2 * g + q;                            // row this thread finalizes
    const int b0      = blockIdx.x * 4;

    // ===== prologue 1: x = latent @ Ws^T + bs for this CTA's 4 rows =====
    float* slat = scr;            // [4*17]
    float* sx   = scr + 128;      // [4][128]
    if (tid < 68) {
        int r = tid / 17, p = tid - r * 17;
        slat[tid] = (p < 16) ? z[(b0 + r) * 16 + p] : c[b0 + r];
    }
    __syncthreads();
    {
        int r = tid >> 7, hcol = tid & 127;   // 512 entries, 1 per thread
        float acc = bs[hcol];
        #pragma unroll
        for (int l = 0; l < 17; l++) acc += Ws[hcol * 17 + l] * slat[r * 17 + l];
        sx[r * 128 + hcol] = acc;
    }
    __syncthreads();

    // ===== prologue 2: xq = xproj (i,f,g,o) for row rq of cell cellj =====
    float4 xq;
    {
        const int j0 = cellj, j1 = cellj + 128, j2 = cellj + 256, j3 = cellj + 384;
        float ai = bih[j0] + bhh[j0];
        float af = bih[j1] + bhh[j1];
        float ag = bih[j2] + bhh[j2];
        float ao = bih[j3] + bhh[j3];
        const float4* wi_ = (const float4*)(Wih + j0 * HID);
        const float4* wf_ = (const float4*)(Wih + j1 * HID);
        const float4* wg_ = (const float4*)(Wih + j2 * HID);
        const float4* wo_ = (const float4*)(Wih + j3 * HID);
        const float4* hx  = (const float4*)(sx + rq * 128);
        #pragma unroll 4
        for (int u = 0; u < 32; u++) {
            float4 x4 = hx[u];
            float4 a = wi_[u], b = wf_[u], d = wg_[u], e = wo_[u];
            ai += a.x*x4.x + a.y*x4.y + a.z*x4.z + a.w*x4.w;
            af += b.x*x4.x + b.y*x4.y + b.z*x4.z + b.w*x4.w;
            ag += d.x*x4.x + d.y*x4.y + d.z*x4.z + d.w*x4.w;
            ao += e.x*x4.x + e.y*x4.y + e.z*x4.z + e.w*x4.w;
        }
        xq = make_float4(ai, af, ag, ao);
    }
    __syncthreads();   // sx dead; hbuf region free

    // ===== weight staging =====
    // gate i (interleaved chunks 2u+q) -> registers
    ull wi[32];
    {
        const ulonglong2* rI = (const ulonglong2*)(Whh + cellj * HID);
        #pragma unroll
        for (int u = 0; u < 16; u++) {
            ulonglong2 t = rI[2*u + q];
            wi[2*u] = t.x; wi[2*u+1] = t.y;
        }
    }
    // gates f,g,o -> smem (only g==0 threads store; slot is g-independent)
    if (g == 0) {
        const ulonglong2* rF = (const ulonglong2*)(Whh + (cellj + 128) * HID);
        const ulonglong2* rG = (const ulonglong2*)(Whh + (cellj + 256) * HID);
        const ulonglong2* rO = (const ulonglong2*)(Whh + (cellj + 384) * HID);
        #pragma unroll
        for (int u = 0; u < 16; u++) {
            wsm[(u*3 + 0) * 256 + slot] = rF[2*u + q];
            wsm[(u*3 + 1) * 256 + slot] = rG[2*u + q];
            wsm[(u*3 + 2) * 256 + slot] = rO[2*u + q];
        }
    }

    // zero both h buffers (2 * 4*HSTR floats, incl. padding)
    for (int i = tid; i < 2 * 4 * HSTR; i += 512) hbuf[i] = 0.f;
    __syncthreads();

    float cc = 0.f;
    float* hsp = g_hs + (size_t)(b0 + rq) * TT * HID + cellj;
    const bool qh = (q != 0);

    int par = 0;
    for (int t = 0; t < TT; t++) {
        // ---- phase A: partial (i,f,g,o) for rows 2g, 2g+1 over K-half q ----
        ull ai[2] = {0,0}, af[2] = {0,0}, ag[2] = {0,0}, ao[2] = {0,0};
        const float* hbp = hbuf + par * (4 * HSTR);
        #pragma unroll
        for (int u = 0; u < 16; u++) {
            ulonglong2 wf = wsm[(u*3 + 0) * 256 + slot];
            ulonglong2 wg = wsm[(u*3 + 1) * 256 + slot];
            ulonglong2 wo = wsm[(u*3 + 2) * 256 + slot];
            #pragma unroll
            for (int rr = 0; rr < 2; rr++) {
                ulonglong2 h2 = ((const ulonglong2*)(hbp + (2*g + rr) * HSTR))[2*u + q];
                ai[rr] = ffma2(wi[2*u],   h2.x, ai[rr]);
                ai[rr] = ffma2(wi[2*u+1], h2.y, ai[rr]);
                af[rr] = ffma2(wf.x,      h2.x, af[rr]);
                af[rr] = ffma2(wf.y,      h2.y, af[rr]);
                ag[rr] = ffma2(wg.x,      h2.x, ag[rr]);
                ag[rr] = ffma2(wg.y,      h2.y, ag[rr]);
                ao[rr] = ffma2(wo.x,      h2.x, ao[rr]);
                ao[rr] = ffma2(wo.y,      h2.y, ao[rr]);
            }
        }
        float si0 = pairsum(ai[0]), si1 = pairsum(ai[1]);
        float sf0 = pairsum(af[0]), sf1 = pairsum(af[1]);
        float sg0 = pairsum(ag[0]), sg1 = pairsum(ag[1]);
        float so0 = pairsum(ao[0]), so1 = pairsum(ao[1]);

        // ---- q-pair shfl reduce: keep row 2g+q, send row 2g+(1-q) ----
        float s, TI, TF, TG, TO;
        s = qh ? si0 : si1;  s = __shfl_xor_sync(0xffffffffu, s, 16);
        TI = (qh ? si1 : si0) + s;
        s = qh ? sf0 : sf1;  s = __shfl_xor_sync(0xffffffffu, s, 16);
        TF = (qh ? sf1 : sf0) + s;
        s = qh ? sg0 : sg1;  s = __shfl_xor_sync(0xffffffffu, s, 16);
        TG = (qh ? sg1 : sg0) + s;
        s = qh ? so0 : so1;  s = __shfl_xor_sync(0xffffffffu, s, 16);
        TO = (qh ? so1 : so0) + s;

        // ---- phase B: activations + cell update for (row rq, cell cellj) ----
        float iv = sigmoidf_(TI + xq.x);
        float fv = sigmoidf_(TF + xq.y);
        float gv = tanhf_  (TG + xq.z);
        float ov = sigmoidf_(TO + xq.w);
        cc = fv * cc + iv * gv;
        float hv = ov * tanhf_(cc);
        hbuf[(par ^ 1) * (4 * HSTR) + rq * HSTR + cellj] = hv;
        __syncthreads();                     // ONE barrier per step
        // deferred global store: overlaps next step's FMA
        hsp[t * HID] = hv;
        par ^= 1;
    }
}

// ---------------- k3: out[b,t,:] = hs[b,t,:] @ Wout^T + bout ----------------
__global__ __launch_bounds__(256)
void k3_out(const float* __restrict__ Wout, const float* __restrict__ bout,
            float* __restrict__ out) {
    __shared__ float4 wsm[OUTD][32];
    __shared__ float bo[OUTD];
    int tid = threadIdx.x;
    for (int i = tid; i < OUTD * 32; i += 256) wsm[i / 32][i % 32] = ((const float4*)Wout)[i];
    if (tid < OUTD) bo[tid] = bout[tid];
    __syncthreads();

    unsigned bt = blockIdx.x * 256 + tid;                // < 524288 exactly
    const float4* hr = (const float4*)(g_hs + (size_t)bt * HID);
    float acc[OUTD];
    #pragma unroll
    for (int o = 0; o < OUTD; o++) acc[o] = bo[o];
    #pragma unroll 4
    for (int u = 0; u < 32; u++) {
        float4 h = hr[u];
        #pragma unroll
        for (int o = 0; o < OUTD; o++) {
            float4 wv = wsm[o][u];
            acc[o] += h.x * wv.x + h.y * wv.y + h.z * wv.z + h.w * wv.w;
        }
    }
    float* op = out + (size_t)bt * OUTD;
    #pragma unroll
    for (int o = 0; o < OUTD; o++) op[o] = acc[o];
}

// ---------------- launcher ----------------
extern "C" void kernel_launch(void* const* d_in, const int* in_sizes, int n_in,
                              void* d_out, int out_size) {
    (void)in_sizes; (void)n_in; (void)out_size;
    const float* z   = (const float*)d_in[0];
    const float* c   = (const float*)d_in[1];
    const float* Ws  = (const float*)d_in[2];
    const float* bs  = (const float*)d_in[3];
    const float* Wih = (const float*)d_in[4];
    const float* bih = (const float*)d_in[5];
    const float* Whh = (const float*)d_in[6];
    const float* bhh = (const float*)d_in[7];
    const float* Wo  = (const float*)d_in[8];
    const float* bo  = (const float*)d_in[9];
    float* out = (float*)d_out;

    cudaFuncSetAttribute(k2_lstm, cudaFuncAttributeMaxDynamicSharedMemorySize, K2_SMEM);

    // 3 no-op launches keep k2 as our 4th launch (ncu captures absolute #6).
    k_nop<<<1, 32>>>();
    k_nop<<<1, 32>>>();
    k_nop<<<1, 32>>>();
    k2_lstm<<<128, 512, K2_SMEM>>>(z, c, Ws, bs, Wih, bih, bhh, Whh);
    k3_out<<<(BATCH * TT) / 256, 256>>>(Wo, bo, out);
}